// round 11
// baseline (speedup 1.0000x reference)
#include <cuda_runtime.h>
#include <math.h>

#define BATCH 16384
#define DIM 4096
#define NUM_EXPERTS 64
#define TOP_K 2

#define NBLOCKS 1184   // 148 SMs x 8 resident CTAs (256 thr, 18 regs)
#define NTHREADS 256

// Output layout: [expanded_x (32768*4096) | indices (32768) | weights (32768)]

__device__ __forceinline__ bool better(float v, int i, float w, int j) {
    return (v > w) || (v == w && i < j);
}

__global__ void __launch_bounds__(NTHREADS) fused_dispatch_kernel(
    const float4* __restrict__ x,
    const float* __restrict__ logits,
    float4* __restrict__ out,
    float* __restrict__ idx_out,
    float* __restrict__ w_out) {

    const int lane = threadIdx.x & 31;
    const int warp = threadIdx.x >> 5;

    // ---------------- Router: distribute rows across all warps ----------------
    // global warp id in [0, NBLOCKS*8); rows strided by total warps (9472).
    const int gwarp = blockIdx.x * (NTHREADS / 32) + warp;
    const int total_warps = NBLOCKS * (NTHREADS / 32);
    for (int row = gwarp; row < BATCH; row += total_warps) {
        const float* l = logits + (size_t)row * NUM_EXPERTS;
        float l0 = l[lane];
        float l1 = l[lane + 32];

        float a, b; int ai, bi;
        if (better(l0, lane, l1, lane + 32)) { a = l0; ai = lane;      b = l1; bi = lane + 32; }
        else                                 { a = l1; ai = lane + 32; b = l0; bi = lane; }

        #pragma unroll
        for (int off = 16; off > 0; off >>= 1) {
            float oa = __shfl_xor_sync(0xffffffffu, a, off);
            int  oai = __shfl_xor_sync(0xffffffffu, ai, off);
            float ob = __shfl_xor_sync(0xffffffffu, b, off);
            int  obi = __shfl_xor_sync(0xffffffffu, bi, off);

            float na, nb; int nai, nbi;
            if (better(a, ai, oa, oai)) {
                na = a; nai = ai;
                if (better(b, bi, oa, oai)) { nb = b;  nbi = bi; }
                else                        { nb = oa; nbi = oai; }
            } else {
                na = oa; nai = oai;
                if (better(a, ai, ob, obi)) { nb = a;  nbi = ai; }
                else                        { nb = ob; nbi = obi; }
            }
            a = na; ai = nai; b = nb; bi = nbi;
        }

        if (lane == 0) {
            // renormalized top-2 softmax: exp(a)/(exp(a)+exp(b)), exp(b)/(...)
            float e = __expf(b - a);          // <= 1, safe
            float inv = 1.0f / (1.0f + e);
            idx_out[row * 2 + 0] = (float)ai;
            idx_out[row * 2 + 1] = (float)bi;
            w_out[row * 2 + 0] = inv;
            w_out[row * 2 + 1] = e * inv;
        }
    }

    // ---------------- Expansion: persistent grid-stride copy ----------------
    const unsigned total_f4 = (unsigned)BATCH * (DIM / 4);   // 16,777,216
    const unsigned stride = NBLOCKS * NTHREADS;              // 303,104
    for (unsigned i = blockIdx.x * NTHREADS + threadIdx.x; i < total_f4; i += stride) {
        const unsigned token = i >> 10;
        const unsigned col   = i & 1023;
        float4 v = __ldcs(&x[i]);
        const size_t base = (size_t)token * 2048 + col;
        __stcs(&out[base],        v);
        __stcs(&out[base + 1024], v);
    }
}

extern "C" void kernel_launch(void* const* d_in, const int* in_sizes, int n_in,
                              void* d_out, int out_size) {
    const float* x      = (const float*)d_in[0];  // [16384, 4096]
    const float* logits = (const float*)d_in[1];  // [16384, 64]
    float* out = (float*)d_out;

    const size_t expanded_elems = (size_t)BATCH * TOP_K * DIM;
    float* idx_out = out + expanded_elems;
    float* w_out   = idx_out + (size_t)BATCH * TOP_K;

    fused_dispatch_kernel<<<NBLOCKS, NTHREADS>>>((const float4*)x, logits,
                                                 (float4*)out, idx_out, w_out);
}

// round 16
// speedup vs baseline: 1.1757x; 1.1757x over previous
#include <cuda_runtime.h>
#include <math.h>

#define BATCH 16384
#define DIM 4096
#define NUM_EXPERTS 64
#define TOP_K 2

#define ROUTER_BLOCKS 256   // scheduled first, hidden under the copy stream
#define NTHREADS 256

// Output layout: [expanded_x (32768*4096) | indices (32768) | weights (32768)]

__device__ __forceinline__ bool better(float v, int i, float w, int j) {
    return (v > w) || (v == w && i < j);
}

__global__ void __launch_bounds__(NTHREADS) fused_dispatch_kernel(
    const float4* __restrict__ x,
    const float* __restrict__ logits,
    float4* __restrict__ out,
    float* __restrict__ idx_out,
    float* __restrict__ w_out) {

    if (blockIdx.x >= ROUTER_BLOCKS) {
        // ---------------- Copy path: branch-free, identical to clean expand ----
        const unsigned i = (blockIdx.x - ROUTER_BLOCKS) * 256u + threadIdx.x;
        const unsigned token = i >> 10;          // 1024 f4 per input row
        const unsigned col   = i & 1023;
        float4 v = __ldcs(&x[i]);
        const size_t base = (size_t)token * 2048 + col;
        __stcs(&out[base],        v);
        __stcs(&out[base + 1024], v);
        return;
    }

    // ---------------- Router path: 256 blocks x 8 warps, 8 rows per warp ------
    const int lane = threadIdx.x & 31;
    const int warp = threadIdx.x >> 5;
    const int gwarp = blockIdx.x * (NTHREADS / 32) + warp;   // 0..2047
    // rows strided: each warp handles rows gwarp, gwarp+2048, ... (8 rows)
    for (int row = gwarp; row < BATCH; row += ROUTER_BLOCKS * (NTHREADS / 32)) {
        const float* l = logits + (size_t)row * NUM_EXPERTS;
        float l0 = l[lane];
        float l1 = l[lane + 32];

        float a, b; int ai, bi;
        if (better(l0, lane, l1, lane + 32)) { a = l0; ai = lane;      b = l1; bi = lane + 32; }
        else                                 { a = l1; ai = lane + 32; b = l0; bi = lane; }

        #pragma unroll
        for (int off = 16; off > 0; off >>= 1) {
            float oa = __shfl_xor_sync(0xffffffffu, a, off);
            int  oai = __shfl_xor_sync(0xffffffffu, ai, off);
            float ob = __shfl_xor_sync(0xffffffffu, b, off);
            int  obi = __shfl_xor_sync(0xffffffffu, bi, off);

            float na, nb; int nai, nbi;
            if (better(a, ai, oa, oai)) {
                na = a; nai = ai;
                if (better(b, bi, oa, oai)) { nb = b;  nbi = bi; }
                else                        { nb = oa; nbi = oai; }
            } else {
                na = oa; nai = oai;
                if (better(a, ai, ob, obi)) { nb = a;  nbi = ai; }
                else                        { nb = ob; nbi = obi; }
            }
            a = na; ai = nai; b = nb; bi = nbi;
        }

        if (lane == 0) {
            // renormalized top-2 softmax: exp(a)/(exp(a)+exp(b)), exp(b)/(...)
            float e = __expf(b - a);          // <= 1, safe
            float inv = 1.0f / (1.0f + e);
            idx_out[row * 2 + 0] = (float)ai;
            idx_out[row * 2 + 1] = (float)bi;
            w_out[row * 2 + 0] = inv;
            w_out[row * 2 + 1] = e * inv;
        }
    }
}

extern "C" void kernel_launch(void* const* d_in, const int* in_sizes, int n_in,
                              void* d_out, int out_size) {
    const float* x      = (const float*)d_in[0];  // [16384, 4096]
    const float* logits = (const float*)d_in[1];  // [16384, 64]
    float* out = (float*)d_out;

    const size_t expanded_elems = (size_t)BATCH * TOP_K * DIM;
    float* idx_out = out + expanded_elems;
    float* w_out   = idx_out + (size_t)BATCH * TOP_K;

    const unsigned copy_blocks = (unsigned)BATCH * (DIM / 4) / NTHREADS;  // 65,536
    fused_dispatch_kernel<<<copy_blocks + ROUTER_BLOCKS, NTHREADS>>>(
        (const float4*)x, logits, (float4*)out, idx_out, w_out);
}